// round 1
// baseline (speedup 1.0000x reference)
#include <cuda_runtime.h>
#include <cuda_bf16.h>
#include <math.h>

// ---------------------------------------------------------------------------
// TopoGCN: 5 x (GEMM -> SpMM -> bias+ReLU) + MLP head.
// Layout (all row-major, fp32):
//   feat   [N, 512]        d_in[0]
//   adj_row[E]             d_in[1]
//   adj_col[E]             d_in[2]
//   adj_val[E]             d_in[3]
//   Wg     [5, 512, 512]   d_in[4]
//   bg     [5, 512]        d_in[5]
//   vw1    [512, 512]      d_in[6]
//   vb1    [512]           d_in[7]
//   vw2    [512, 1]        d_in[8]
//   vb2    [1]             d_in[9]
//   out    [N, 1] fp32
// ---------------------------------------------------------------------------

#define HID 512
#define MAXN 10048          // 10000 rounded up

// Scratch (static device globals; no allocation allowed)
__device__ float g_h[MAXN * HID];     // GEMM output of current layer
__device__ float g_agg[MAXN * HID];   // SpMM accumulator
__device__ float g_x[MAXN * HID];     // layer activation

// ---------------------------------------------------------------------------
// SGEMM: C[M,512] = A[M,512] @ B[512,512], optional epilogue bias+ReLU.
// BM=128, BN=128, BK=8, 256 threads, 8x8 micro-tile per thread.
// ---------------------------------------------------------------------------
#define BM 128
#define BN 128
#define BK 8
#define TM 8
#define TN 8

template <int MODE>  // 0 = plain store, 1 = bias + relu
__global__ __launch_bounds__(256, 2)
void sgemm512(const float* __restrict__ A, const float* __restrict__ B,
              float* __restrict__ C, const float* __restrict__ bias, int M) {
    __shared__ float As[BK][BM];
    __shared__ float Bs[BK][BN];

    const int t   = threadIdx.x;
    const int m0  = blockIdx.y * BM;
    const int n0  = blockIdx.x * BN;

    const int tx = t & 15;        // 0..15
    const int ty = t >> 4;        // 0..15
    const int cRow = ty * TM;     // row offset in tile
    const int cCol = tx * TN;     // col offset in tile

    // A-tile load mapping: 2 float4 per row of 8 -> thread t loads row t/2, col4 (t&1)*4
    const int aRow  = t >> 1;
    const int aCol4 = (t & 1) * 4;
    // B-tile load mapping: row t/32 (0..7), col4 (t&31)*4
    const int bRow  = t >> 5;
    const int bCol4 = (t & 31) * 4;

    float acc[TM][TN];
#pragma unroll
    for (int i = 0; i < TM; ++i)
#pragma unroll
        for (int j = 0; j < TN; ++j) acc[i][j] = 0.0f;

    for (int k0 = 0; k0 < HID; k0 += BK) {
        // load A tile (transposed into As[k][m]), guard M
        float4 av = make_float4(0.f, 0.f, 0.f, 0.f);
        int gRow = m0 + aRow;
        if (gRow < M)
            av = *reinterpret_cast<const float4*>(&A[(size_t)gRow * HID + k0 + aCol4]);
        As[aCol4 + 0][aRow] = av.x;
        As[aCol4 + 1][aRow] = av.y;
        As[aCol4 + 2][aRow] = av.z;
        As[aCol4 + 3][aRow] = av.w;

        // load B tile
        float4 bv = *reinterpret_cast<const float4*>(&B[(size_t)(k0 + bRow) * HID + n0 + bCol4]);
        *reinterpret_cast<float4*>(&Bs[bRow][bCol4]) = bv;

        __syncthreads();

        float regM[TM], regN[TN];
#pragma unroll
        for (int k = 0; k < BK; ++k) {
#pragma unroll
            for (int i = 0; i < TM; ++i) regM[i] = As[k][cRow + i];
#pragma unroll
            for (int j = 0; j < TN; ++j) regN[j] = Bs[k][cCol + j];
#pragma unroll
            for (int i = 0; i < TM; ++i)
#pragma unroll
                for (int j = 0; j < TN; ++j)
                    acc[i][j] = fmaf(regM[i], regN[j], acc[i][j]);
        }
        __syncthreads();
    }

    // epilogue
#pragma unroll
    for (int i = 0; i < TM; ++i) {
        int row = m0 + cRow + i;
        if (row >= M) continue;
#pragma unroll
        for (int j4 = 0; j4 < TN; j4 += 4) {
            int col = n0 + cCol + j4;
            float4 v;
            v.x = acc[i][j4 + 0];
            v.y = acc[i][j4 + 1];
            v.z = acc[i][j4 + 2];
            v.w = acc[i][j4 + 3];
            if (MODE == 1) {
                v.x = fmaxf(v.x + bias[col + 0], 0.f);
                v.y = fmaxf(v.y + bias[col + 1], 0.f);
                v.z = fmaxf(v.z + bias[col + 2], 0.f);
                v.w = fmaxf(v.w + bias[col + 3], 0.f);
            }
            *reinterpret_cast<float4*>(&C[(size_t)row * HID + col]) = v;
        }
    }
}

// ---------------------------------------------------------------------------
// zero g_agg
// ---------------------------------------------------------------------------
__global__ void zero_agg(int n4) {
    int i = blockIdx.x * blockDim.x + threadIdx.x;
    if (i < n4) reinterpret_cast<float4*>(g_agg)[i] = make_float4(0.f, 0.f, 0.f, 0.f);
}

// ---------------------------------------------------------------------------
// SpMM: for each edge e: agg[row[e], :] += val[e] * h[col[e], :]
// one block (128 threads) per edge; 4 floats per thread via float4 read +
// 4 scalar red.add (no return -> REDG).
// ---------------------------------------------------------------------------
__global__ __launch_bounds__(128)
void spmm_edges(const int* __restrict__ row, const int* __restrict__ col,
                const float* __restrict__ val, int E) {
    int e = blockIdx.x;
    if (e >= E) return;
    int r = row[e];
    int c = col[e];
    float v = val[e];
    const float4* hp = reinterpret_cast<const float4*>(&g_h[(size_t)c * HID]);
    float* ap = &g_agg[(size_t)r * HID];
    int t = threadIdx.x;            // 0..127
    float4 hv = hp[t];
    int base = t * 4;
    atomicAdd(ap + base + 0, v * hv.x);
    atomicAdd(ap + base + 1, v * hv.y);
    atomicAdd(ap + base + 2, v * hv.z);
    atomicAdd(ap + base + 3, v * hv.w);
}

// ---------------------------------------------------------------------------
// x = relu(agg + bg_layer)
// ---------------------------------------------------------------------------
__global__ void bias_relu(const float* __restrict__ bias, int n4) {
    int i = blockIdx.x * blockDim.x + threadIdx.x;
    if (i >= n4) return;
    float4 a = reinterpret_cast<const float4*>(g_agg)[i];
    int col = (i * 4) & (HID - 1);
    a.x = fmaxf(a.x + bias[col + 0], 0.f);
    a.y = fmaxf(a.y + bias[col + 1], 0.f);
    a.z = fmaxf(a.z + bias[col + 2], 0.f);
    a.w = fmaxf(a.w + bias[col + 3], 0.f);
    reinterpret_cast<float4*>(g_x)[i] = a;
}

// ---------------------------------------------------------------------------
// head2: out[r] = sigmoid(dot(h[r,:], w) + b)   (one warp per row)
// ---------------------------------------------------------------------------
__global__ void head2(const float* __restrict__ w, const float* __restrict__ b,
                      float* __restrict__ out, int M) {
    int warp = (blockIdx.x * blockDim.x + threadIdx.x) >> 5;
    int lane = threadIdx.x & 31;
    if (warp >= M) return;
    const float* hr = &g_h[(size_t)warp * HID];
    float s = 0.f;
#pragma unroll
    for (int k = lane * 4; k < HID; k += 32 * 4) {
        float4 hv = *reinterpret_cast<const float4*>(&hr[k]);
        float4 wv = *reinterpret_cast<const float4*>(&w[k]);
        s = fmaf(hv.x, wv.x, s);
        s = fmaf(hv.y, wv.y, s);
        s = fmaf(hv.z, wv.z, s);
        s = fmaf(hv.w, wv.w, s);
    }
#pragma unroll
    for (int off = 16; off > 0; off >>= 1)
        s += __shfl_down_sync(0xffffffffu, s, off);
    if (lane == 0) {
        float z = s + b[0];
        out[warp] = 1.0f / (1.0f + expf(-z));
    }
}

// ---------------------------------------------------------------------------
// launch
// ---------------------------------------------------------------------------
extern "C" void kernel_launch(void* const* d_in, const int* in_sizes, int n_in,
                              void* d_out, int out_size) {
    const float* feat    = (const float*)d_in[0];
    const int*   adj_row = (const int*)d_in[1];
    const int*   adj_col = (const int*)d_in[2];
    const float* adj_val = (const float*)d_in[3];
    const float* Wg      = (const float*)d_in[4];
    const float* bg      = (const float*)d_in[5];
    const float* vw1     = (const float*)d_in[6];
    const float* vb1     = (const float*)d_in[7];
    const float* vw2     = (const float*)d_in[8];
    const float* vb2     = (const float*)d_in[9];
    float*       out     = (float*)d_out;

    const int M = in_sizes[0] / HID;   // 10000
    const int E = in_sizes[1];         // 160000
    const int n4 = (M * HID) / 4;

    // device-symbol addresses for GEMM args
    float* h_ptr;   cudaGetSymbolAddress((void**)&h_ptr,   g_h);
    float* x_ptr;   cudaGetSymbolAddress((void**)&x_ptr,   g_x);

    dim3 gemmGrid(HID / BN, (M + BM - 1) / BM);
    dim3 gemmBlock(256);

    const float* x_in = feat;
    for (int layer = 0; layer < 5; ++layer) {
        // h = x @ Wg[layer]
        sgemm512<0><<<gemmGrid, gemmBlock>>>(x_in, Wg + (size_t)layer * HID * HID,
                                             h_ptr, nullptr, M);
        // agg = 0
        zero_agg<<<(n4 + 255) / 256, 256>>>(n4);
        // agg += A @ h (edge scatter)
        spmm_edges<<<E, 128>>>(adj_row, adj_col, adj_val, E);
        // x = relu(agg + bg[layer])
        bias_relu<<<(n4 + 255) / 256, 256>>>(bg + (size_t)layer * HID, n4);
        x_in = x_ptr;
    }

    // h = relu(x @ vw1 + vb1)
    sgemm512<1><<<gemmGrid, gemmBlock>>>(x_ptr, vw1, h_ptr, vb1, M);
    // out = sigmoid(h @ vw2 + vb2)
    head2<<<(M * 32 + 255) / 256, 256>>>(vw2, vb2, out, M);
}

// round 3
// speedup vs baseline: 1.9872x; 1.9872x over previous
#include <cuda_runtime.h>
#include <cuda_bf16.h>
#include <math.h>

// ---------------------------------------------------------------------------
// TopoGCN: 5 x (GEMM -> SpMM -> bias+ReLU) + MLP head.
// fp32 row-major. See metadata order in kernel_launch.
// This round: CSR gather SpMM (no global atomics) + FFMA2 (f32x2) SGEMM.
// ---------------------------------------------------------------------------

#define HID 512
#define MAXN 10048
#define MAXE 160000

typedef unsigned long long u64;

// Scratch (static device globals; allocation is forbidden)
__device__ float g_h[MAXN * HID];      // GEMM output of current layer
__device__ float g_x[MAXN * HID];      // layer activation
__device__ int   g_cnt[MAXN];          // CSR: per-row edge count
__device__ int   g_off[MAXN + 1];      // CSR: row offsets
__device__ int   g_cur[MAXN];          // CSR: scatter cursors
__device__ int   g_scol[MAXE];         // edges sorted by row: col
__device__ float g_sval[MAXE];         // edges sorted by row: val

// ---------------------------------------------------------------------------
// f32x2 helpers (PTX-only packed fp32 FMA)
// ---------------------------------------------------------------------------
__device__ __forceinline__ u64 pack2_dup(float a) {
    u64 r;
    asm("mov.b64 %0, {%1, %1};" : "=l"(r) : "f"(a));
    return r;
}
__device__ __forceinline__ void fma2(u64& d, u64 a, u64 b) {
    asm("fma.rn.f32x2 %0, %1, %2, %0;" : "+l"(d) : "l"(a), "l"(b));
}
__device__ __forceinline__ void unpack2(u64 v, float& lo, float& hi) {
    asm("mov.b64 {%0, %1}, %2;" : "=f"(lo), "=f"(hi) : "l"(v));
}

// ---------------------------------------------------------------------------
// SGEMM: C[M,512] = A[M,512] @ B[512,512], optional bias+ReLU epilogue.
// BM=BN=128, BK=8, 256 threads. Per thread: 8 rows x 8 cols, cols packed in
// f32x2 pairs at stride 32 (conflict-free LDS.64 on Bs).
// ---------------------------------------------------------------------------
#define BM 128
#define BN 128
#define BK 8
#define TM 8

template <int MODE>  // 0 = plain store, 1 = bias + relu
__global__ __launch_bounds__(256, 2)
void sgemm512(const float* __restrict__ A, const float* __restrict__ B,
              float* __restrict__ C, const float* __restrict__ bias, int M) {
    __shared__ float As[BK][BM];
    __shared__ float Bs[BK][BN];

    const int t  = threadIdx.x;
    const int m0 = blockIdx.y * BM;
    const int n0 = blockIdx.x * BN;

    const int tx = t & 15;         // 0..15
    const int ty = t >> 4;         // 0..15
    const int cRow  = ty * TM;     // row offset in tile
    const int cCol2 = tx * 2;      // base col: pairs at stride 32

    // A-tile load: thread t loads row t/2, 4 floats at (t&1)*4
    const int aRow  = t >> 1;
    const int aCol4 = (t & 1) * 4;
    // B-tile load: row t/32, 4 floats at (t&31)*4
    const int bRow  = t >> 5;
    const int bCol4 = (t & 31) * 4;

    u64 acc[TM][4];
#pragma unroll
    for (int i = 0; i < TM; ++i)
#pragma unroll
        for (int j = 0; j < 4; ++j) acc[i][j] = 0ull;

    for (int k0 = 0; k0 < HID; k0 += BK) {
        float4 av = make_float4(0.f, 0.f, 0.f, 0.f);
        int gRow = m0 + aRow;
        if (gRow < M)
            av = *reinterpret_cast<const float4*>(&A[(size_t)gRow * HID + k0 + aCol4]);
        As[aCol4 + 0][aRow] = av.x;
        As[aCol4 + 1][aRow] = av.y;
        As[aCol4 + 2][aRow] = av.z;
        As[aCol4 + 3][aRow] = av.w;

        float4 bv = *reinterpret_cast<const float4*>(&B[(size_t)(k0 + bRow) * HID + n0 + bCol4]);
        *reinterpret_cast<float4*>(&Bs[bRow][bCol4]) = bv;

        __syncthreads();

#pragma unroll
        for (int k = 0; k < BK; ++k) {
            u64 bn[4];
#pragma unroll
            for (int j = 0; j < 4; ++j)
                bn[j] = *reinterpret_cast<const u64*>(&Bs[k][cCol2 + 32 * j]);
            u64 am[TM];
#pragma unroll
            for (int i = 0; i < TM; ++i)
                am[i] = pack2_dup(As[k][cRow + i]);
#pragma unroll
            for (int i = 0; i < TM; ++i)
#pragma unroll
                for (int j = 0; j < 4; ++j)
                    fma2(acc[i][j], am[i], bn[j]);
        }
        __syncthreads();
    }

    // epilogue: each (i,j) pair -> columns n0 + cCol2 + 32j + {0,1}
#pragma unroll
    for (int i = 0; i < TM; ++i) {
        int row = m0 + cRow + i;
        if (row >= M) continue;
#pragma unroll
        for (int j = 0; j < 4; ++j) {
            int col = n0 + cCol2 + 32 * j;
            float lo, hi;
            unpack2(acc[i][j], lo, hi);
            if (MODE == 1) {
                lo = fmaxf(lo + bias[col + 0], 0.f);
                hi = fmaxf(hi + bias[col + 1], 0.f);
            }
            float2 v = make_float2(lo, hi);
            *reinterpret_cast<float2*>(&C[(size_t)row * HID + col]) = v;
        }
    }
}

// ---------------------------------------------------------------------------
// CSR build (once per launch; topology is layer-invariant)
// ---------------------------------------------------------------------------
__global__ void csr_zero(int n) {
    int i = blockIdx.x * blockDim.x + threadIdx.x;
    if (i < n) g_cnt[i] = 0;
}

__global__ void csr_hist(const int* __restrict__ row, int E) {
    int e = blockIdx.x * blockDim.x + threadIdx.x;
    if (e < E) atomicAdd(&g_cnt[row[e]], 1);
}

__global__ __launch_bounds__(1024)
void csr_scan(int n) {  // single block
    __shared__ int warp_sums[32];
    const int t = threadIdx.x;
    const int per = (n + 1023) / 1024;
    const int base = t * per;

    int local[16];
    int sum = 0;
#pragma unroll 4
    for (int i = 0; i < per; ++i) {
        int idx = base + i;
        int v = (idx < n) ? g_cnt[idx] : 0;
        local[i] = sum;
        sum += v;
    }
    const int lane = t & 31, wid = t >> 5;
    int s = sum;
#pragma unroll
    for (int o = 1; o < 32; o <<= 1) {
        int u = __shfl_up_sync(0xffffffffu, s, o);
        if (lane >= o) s += u;
    }
    if (lane == 31) warp_sums[wid] = s;
    __syncthreads();
    if (wid == 0) {
        int ws = warp_sums[lane];
#pragma unroll
        for (int o = 1; o < 32; o <<= 1) {
            int u = __shfl_up_sync(0xffffffffu, ws, o);
            if (lane >= o) ws += u;
        }
        warp_sums[lane] = ws;
    }
    __syncthreads();
    int excl = (s - sum) + (wid > 0 ? warp_sums[wid - 1] : 0);
#pragma unroll 4
    for (int i = 0; i < per; ++i) {
        int idx = base + i;
        if (idx < n) {
            int off = excl + local[i];
            g_off[idx] = off;
            g_cur[idx] = off;
        }
    }
    if (t == 1023) g_off[n] = excl + sum;
}

__global__ void csr_scatter(const int* __restrict__ row, const int* __restrict__ col,
                            const float* __restrict__ val, int E) {
    int e = blockIdx.x * blockDim.x + threadIdx.x;
    if (e >= E) return;
    int r = row[e];
    int slot = atomicAdd(&g_cur[r], 1);
    g_scol[slot] = col[e];
    g_sval[slot] = val[e];
}

// ---------------------------------------------------------------------------
// SpMM gather + bias + ReLU fused: x[r] = relu(sum_e val*h[col] + bias)
// One block (128 threads) per row; float4 per thread; no atomics.
// ---------------------------------------------------------------------------
__global__ __launch_bounds__(128)
void spmm_gather(const float* __restrict__ bias) {
    const int r = blockIdx.x;
    const int t = threadIdx.x;
    const int beg = g_off[r];
    const int end = g_off[r + 1];
    const int c4 = t * 4;

    float4 a0 = make_float4(0.f, 0.f, 0.f, 0.f);
    float4 a1 = make_float4(0.f, 0.f, 0.f, 0.f);

    int j = beg;
    for (; j + 1 < end; j += 2) {
        int   c0 = g_scol[j],     c1 = g_scol[j + 1];
        float v0 = g_sval[j],     v1 = g_sval[j + 1];
        float4 h0 = *reinterpret_cast<const float4*>(&g_h[(size_t)c0 * HID + c4]);
        float4 h1 = *reinterpret_cast<const float4*>(&g_h[(size_t)c1 * HID + c4]);
        a0.x = fmaf(v0, h0.x, a0.x);  a0.y = fmaf(v0, h0.y, a0.y);
        a0.z = fmaf(v0, h0.z, a0.z);  a0.w = fmaf(v0, h0.w, a0.w);
        a1.x = fmaf(v1, h1.x, a1.x);  a1.y = fmaf(v1, h1.y, a1.y);
        a1.z = fmaf(v1, h1.z, a1.z);  a1.w = fmaf(v1, h1.w, a1.w);
    }
    if (j < end) {
        int   c0 = g_scol[j];
        float v0 = g_sval[j];
        float4 h0 = *reinterpret_cast<const float4*>(&g_h[(size_t)c0 * HID + c4]);
        a0.x = fmaf(v0, h0.x, a0.x);  a0.y = fmaf(v0, h0.y, a0.y);
        a0.z = fmaf(v0, h0.z, a0.z);  a0.w = fmaf(v0, h0.w, a0.w);
    }

    float4 b = *reinterpret_cast<const float4*>(&bias[c4]);
    float4 o;
    o.x = fmaxf(a0.x + a1.x + b.x, 0.f);
    o.y = fmaxf(a0.y + a1.y + b.y, 0.f);
    o.z = fmaxf(a0.z + a1.z + b.z, 0.f);
    o.w = fmaxf(a0.w + a1.w + b.w, 0.f);
    *reinterpret_cast<float4*>(&g_x[(size_t)r * HID + c4]) = o;
}

// ---------------------------------------------------------------------------
// head2: out[r] = sigmoid(dot(h[r,:], w) + b)   (one warp per row)
// ---------------------------------------------------------------------------
__global__ void head2(const float* __restrict__ w, const float* __restrict__ b,
                      float* __restrict__ out, int M) {
    int warp = (blockIdx.x * blockDim.x + threadIdx.x) >> 5;
    int lane = threadIdx.x & 31;
    if (warp >= M) return;
    const float* hr = &g_h[(size_t)warp * HID];
    float s = 0.f;
#pragma unroll
    for (int k = lane * 4; k < HID; k += 32 * 4) {
        float4 hv = *reinterpret_cast<const float4*>(&hr[k]);
        float4 wv = *reinterpret_cast<const float4*>(&w[k]);
        s = fmaf(hv.x, wv.x, s);
        s = fmaf(hv.y, wv.y, s);
        s = fmaf(hv.z, wv.z, s);
        s = fmaf(hv.w, wv.w, s);
    }
#pragma unroll
    for (int off = 16; off > 0; off >>= 1)
        s += __shfl_down_sync(0xffffffffu, s, off);
    if (lane == 0) {
        float z = s + b[0];
        out[warp] = 1.0f / (1.0f + expf(-z));
    }
}

// ---------------------------------------------------------------------------
// launch
// ---------------------------------------------------------------------------
extern "C" void kernel_launch(void* const* d_in, const int* in_sizes, int n_in,
                              void* d_out, int out_size) {
    const float* feat    = (const float*)d_in[0];
    const int*   adj_row = (const int*)d_in[1];
    const int*   adj_col = (const int*)d_in[2];
    const float* adj_val = (const float*)d_in[3];
    const float* Wg      = (const float*)d_in[4];
    const float* bg      = (const float*)d_in[5];
    const float* vw1     = (const float*)d_in[6];
    const float* vb1     = (const float*)d_in[7];
    const float* vw2     = (const float*)d_in[8];
    const float* vb2     = (const float*)d_in[9];
    float*       out     = (float*)d_out;

    const int M = in_sizes[0] / HID;   // 10000
    const int E = in_sizes[1];         // 160000

    float* h_ptr;   cudaGetSymbolAddress((void**)&h_ptr, g_h);
    float* x_ptr;   cudaGetSymbolAddress((void**)&x_ptr, g_x);

    // --- CSR build (topology is shared by all 5 layers) ---
    csr_zero<<<(M + 255) / 256, 256>>>(M);
    csr_hist<<<(E + 255) / 256, 256>>>(adj_row, E);
    csr_scan<<<1, 1024>>>(M);
    csr_scatter<<<(E + 255) / 256, 256>>>(adj_row, adj_col, adj_val, E);

    dim3 gemmGrid(HID / BN, (M + BM - 1) / BM);
    dim3 gemmBlock(256);

    const float* x_in = feat;
    for (int layer = 0; layer < 5; ++layer) {
        sgemm512<0><<<gemmGrid, gemmBlock>>>(x_in, Wg + (size_t)layer * HID * HID,
                                             h_ptr, nullptr, M);
        spmm_gather<<<M, 128>>>(bg + (size_t)layer * HID);
        x_in = x_ptr;
    }

    // h = relu(x @ vw1 + vb1)
    sgemm512<1><<<gemmGrid, gemmBlock>>>(x_ptr, vw1, h_ptr, vb1, M);
    // out = sigmoid(h @ vw2 + vb2)
    head2<<<(M * 32 + 255) / 256, 256>>>(vw2, vb2, out, M);
}

// round 6
// speedup vs baseline: 3.3414x; 1.6815x over previous
#include <cuda_runtime.h>
#include <cuda_bf16.h>
#include <math.h>
#include <stdint.h>

// ---------------------------------------------------------------------------
// TopoGCN: 5 x (GEMM -> SpMM -> bias+ReLU) + MLP head.
// This round: warp-level HMMA (mma.sync bf16, base PTX - no 'a' features),
// bf16 split-2 three-product GEMM, CSR gather SpMM.
// ---------------------------------------------------------------------------

#define HID 512
#define MAXN 10048
#define MAXE 160000

// Scratch (static device globals; allocation is forbidden)
__device__ float          g_h[MAXN * HID];        // GEMM out (fp32)
__device__ __nv_bfloat16  g_xh[MAXN * HID];       // activation hi (bf16)
__device__ __nv_bfloat16  g_xl[MAXN * HID];       // activation lo (bf16)
__device__ __nv_bfloat16  g_wh[6 * HID * HID];    // W^T hi (bf16) [n][k], 6 slots
__device__ __nv_bfloat16  g_wl[6 * HID * HID];    // W^T lo
__device__ int   g_cnt[MAXN];
__device__ int   g_off[MAXN + 1];
__device__ int   g_cur[MAXN];
__device__ int   g_scol[MAXE];
__device__ float g_sval[MAXE];

__device__ __forceinline__ uint32_t smem_u32(const void* p) {
    uint32_t a;
    asm("{ .reg .u64 t; cvta.to.shared.u64 t, %1; cvt.u32.u64 %0, t; }" : "=r"(a) : "l"(p));
    return a;
}

// ---------------------------------------------------------------------------
// HMMA GEMM: C[M,512] = A[M,512] @ W  (W given as W^T[n][k] bf16 hi/lo).
// 3 products: Ah*Bh + Ah*Bl + Al*Bh accumulated in fp32 fragments.
// Block 128x128, 8 warps (4m x 2n), warp tile 32x64, BK=32, double-buffered
// cp.async. SMEM rows padded to 80B (conflict-free ldmatrix).
// ---------------------------------------------------------------------------
#define BM 128
#define BN 128
#define BKC 32
#define ROWSTRIDE 80                 // bytes per smem row: 32 bf16 + 8 pad
#define A_OFF 0
#define B_OFF (128 * ROWSTRIDE)      // 10240
#define STAGE_BYTES (2 * 128 * ROWSTRIDE)  // 20480

#define LDM_X4(r, addr) \
    asm volatile("ldmatrix.sync.aligned.m8n8.x4.shared.b16 {%0,%1,%2,%3}, [%4];" \
                 : "=r"((r)[0]), "=r"((r)[1]), "=r"((r)[2]), "=r"((r)[3]) : "r"(addr))

#define MMA16816(c, a, b0, b1) \
    asm volatile("mma.sync.aligned.m16n8k16.row.col.f32.bf16.bf16.f32 " \
                 "{%0,%1,%2,%3}, {%4,%5,%6,%7}, {%8,%9}, {%0,%1,%2,%3};" \
                 : "+f"((c)[0]), "+f"((c)[1]), "+f"((c)[2]), "+f"((c)[3]) \
                 : "r"((a)[0]), "r"((a)[1]), "r"((a)[2]), "r"((a)[3]), "r"(b0), "r"(b1))

template <int MODE>  // 0 = plain store, 1 = bias + relu
__global__ __launch_bounds__(256, 2)
void gemm_hmma(const __nv_bfloat16* __restrict__ Ah, const __nv_bfloat16* __restrict__ Al,
               const __nv_bfloat16* __restrict__ Bh, const __nv_bfloat16* __restrict__ Bl,
               float* __restrict__ C, const float* __restrict__ bias, int M) {
    __shared__ __align__(16) char smem[2 * STAGE_BYTES];
    const uint32_t sb = smem_u32(smem);
    const int t = threadIdx.x;
    const int wid = t >> 5, lane = t & 31;
    const int m0 = blockIdx.y * BM, n0 = blockIdx.x * BN;
    const int wm = wid & 3, wn = wid >> 2;

    const __nv_bfloat16* Aptr[3] = {Ah, Ah, Al};
    const __nv_bfloat16* Bptr[3] = {Bh, Bl, Bh};

    float acc[2][8][4];
#pragma unroll
    for (int i = 0; i < 2; ++i)
#pragma unroll
        for (int j = 0; j < 8; ++j)
#pragma unroll
            for (int q = 0; q < 4; ++q) acc[i][j][q] = 0.0f;

    // per-thread load slots: A: 128 rows x 4 chunks of 16B; same for B.
    const int aRow0 = t >> 2;            // handles rows t>>2 and 64 + (t>>2)
    const int aKc   = (t & 3) * 8;       // bf16 offset of 16B chunk

    auto issue = [&](int c) {
        const int ph = c >> 4;
        const int k0 = (c & 15) * BKC;
        const uint32_t buf = sb + (c & 1) * STAGE_BYTES;
        const __nv_bfloat16* A = Aptr[ph];
        const __nv_bfloat16* B = Bptr[ph];
#pragma unroll
        for (int h = 0; h < 2; ++h) {
            int row = aRow0 + h * 64;
            uint32_t dst = buf + A_OFF + row * ROWSTRIDE + aKc * 2;
            const void* src = A + (size_t)(m0 + row) * HID + k0 + aKc;
            int sz = (m0 + row < M) ? 16 : 0;
            asm volatile("cp.async.cg.shared.global [%0], [%1], 16, %2;"
                         :: "r"(dst), "l"(src), "r"(sz));
        }
#pragma unroll
        for (int h = 0; h < 2; ++h) {
            int row = aRow0 + h * 64;
            uint32_t dst = buf + B_OFF + row * ROWSTRIDE + aKc * 2;
            const void* src = B + (size_t)(n0 + row) * HID + k0 + aKc;
            asm volatile("cp.async.cg.shared.global [%0], [%1], 16;"
                         :: "r"(dst), "l"(src));
        }
        asm volatile("cp.async.commit_group;" ::: "memory");
    };

    issue(0);
    for (int c = 0; c < 48; ++c) {
        if (c + 1 < 48) {
            issue(c + 1);
            asm volatile("cp.async.wait_group 1;" ::: "memory");
        } else {
            asm volatile("cp.async.wait_group 0;" ::: "memory");
        }
        __syncthreads();

        const uint32_t buf = sb + (c & 1) * STAGE_BYTES;
#pragma unroll
        for (int ks = 0; ks < 2; ++ks) {
            uint32_t a[2][4], b[4][4];
#pragma unroll
            for (int i = 0; i < 2; ++i) {
                int row = wm * 32 + i * 16 + (lane & 15);
                uint32_t addr = buf + A_OFF + row * ROWSTRIDE + ks * 32 + ((lane >> 4) << 4);
                LDM_X4(a[i], addr);
            }
#pragma unroll
            for (int j2 = 0; j2 < 4; ++j2) {
                int q = lane >> 3, r = lane & 7;
                int n = wn * 64 + j2 * 16 + ((q >> 1) << 3) + r;
                uint32_t addr = buf + B_OFF + n * ROWSTRIDE + ks * 32 + ((q & 1) << 4);
                LDM_X4(b[j2], addr);
            }
#pragma unroll
            for (int i = 0; i < 2; ++i)
#pragma unroll
                for (int j = 0; j < 8; ++j) {
                    const uint32_t* bb = b[j >> 1];
                    if (j & 1) MMA16816(acc[i][j], a[i], bb[2], bb[3]);
                    else       MMA16816(acc[i][j], a[i], bb[0], bb[1]);
                }
        }
        __syncthreads();
    }

    // epilogue: c0,c1 at (row, col..col+1); c2,c3 at (row+8, ...)
#pragma unroll
    for (int i = 0; i < 2; ++i) {
        int rowA = m0 + wm * 32 + i * 16 + (lane >> 2);
        int rowB = rowA + 8;
#pragma unroll
        for (int j = 0; j < 8; ++j) {
            int col = n0 + wn * 64 + j * 8 + (lane & 3) * 2;
            float2 v0 = make_float2(acc[i][j][0], acc[i][j][1]);
            float2 v1 = make_float2(acc[i][j][2], acc[i][j][3]);
            if (MODE == 1) {
                float b0 = bias[col], b1 = bias[col + 1];
                v0.x = fmaxf(v0.x + b0, 0.f);  v0.y = fmaxf(v0.y + b1, 0.f);
                v1.x = fmaxf(v1.x + b0, 0.f);  v1.y = fmaxf(v1.y + b1, 0.f);
            }
            if (rowA < M) *reinterpret_cast<float2*>(&C[(size_t)rowA * HID + col]) = v0;
            if (rowB < M) *reinterpret_cast<float2*>(&C[(size_t)rowB * HID + col]) = v1;
        }
    }
}

// ---------------------------------------------------------------------------
// Weight transpose + bf16 split: g_wh/g_wl[slot][n][k] = split(W[k][n])
// ---------------------------------------------------------------------------
__global__ void wconv(const float* __restrict__ Wg, const float* __restrict__ vw1) {
    __shared__ float ts[32][33];
    const int s = blockIdx.z;
    const float* src = (s < 5) ? Wg + (size_t)s * HID * HID : vw1;
    const int n0 = blockIdx.x * 32, k0 = blockIdx.y * 32;
#pragma unroll
    for (int i = 0; i < 32; i += 8) {
        int k = k0 + threadIdx.y + i;
        ts[threadIdx.y + i][threadIdx.x] = src[(size_t)k * HID + n0 + threadIdx.x];
    }
    __syncthreads();
    size_t sbase = (size_t)s * HID * HID;
#pragma unroll
    for (int i = 0; i < 32; i += 8) {
        int n = n0 + threadIdx.y + i;
        float v = ts[threadIdx.x][threadIdx.y + i];  // = W[k0+tx][n]
        __nv_bfloat16 hi = __float2bfloat16(v);
        __nv_bfloat16 lo = __float2bfloat16(v - __bfloat162float(hi));
        g_wh[sbase + (size_t)n * HID + k0 + threadIdx.x] = hi;
        g_wl[sbase + (size_t)n * HID + k0 + threadIdx.x] = lo;
    }
}

// ---------------------------------------------------------------------------
// Activation split for feat: g_xh/g_xl = split(src)
// ---------------------------------------------------------------------------
__global__ void conv_act(const float* __restrict__ src, int n4) {
    int i = blockIdx.x * blockDim.x + threadIdx.x;
    if (i >= n4) return;
    float4 v = reinterpret_cast<const float4*>(src)[i];
    __nv_bfloat16 h0 = __float2bfloat16(v.x), h1 = __float2bfloat16(v.y);
    __nv_bfloat16 h2 = __float2bfloat16(v.z), h3 = __float2bfloat16(v.w);
    __nv_bfloat16 l0 = __float2bfloat16(v.x - __bfloat162float(h0));
    __nv_bfloat16 l1 = __float2bfloat16(v.y - __bfloat162float(h1));
    __nv_bfloat16 l2 = __float2bfloat16(v.z - __bfloat162float(h2));
    __nv_bfloat16 l3 = __float2bfloat16(v.w - __bfloat162float(h3));
    ushort4 hv = make_ushort4(__bfloat16_as_ushort(h0), __bfloat16_as_ushort(h1),
                              __bfloat16_as_ushort(h2), __bfloat16_as_ushort(h3));
    ushort4 lv = make_ushort4(__bfloat16_as_ushort(l0), __bfloat16_as_ushort(l1),
                              __bfloat16_as_ushort(l2), __bfloat16_as_ushort(l3));
    *reinterpret_cast<ushort4*>(&g_xh[i * 4]) = hv;
    *reinterpret_cast<ushort4*>(&g_xl[i * 4]) = lv;
}

// ---------------------------------------------------------------------------
// CSR build (once per launch)
// ---------------------------------------------------------------------------
__global__ void csr_zero(int n) {
    int i = blockIdx.x * blockDim.x + threadIdx.x;
    if (i < n) g_cnt[i] = 0;
}
__global__ void csr_hist(const int* __restrict__ row, int E) {
    int e = blockIdx.x * blockDim.x + threadIdx.x;
    if (e < E) atomicAdd(&g_cnt[row[e]], 1);
}
__global__ __launch_bounds__(1024)
void csr_scan(int n) {
    __shared__ int warp_sums[32];
    const int t = threadIdx.x;
    const int per = (n + 1023) / 1024;
    const int base = t * per;
    int local[16];
    int sum = 0;
#pragma unroll 4
    for (int i = 0; i < per; ++i) {
        int idx = base + i;
        int v = (idx < n) ? g_cnt[idx] : 0;
        local[i] = sum;
        sum += v;
    }
    const int lane = t & 31, wid = t >> 5;
    int s = sum;
#pragma unroll
    for (int o = 1; o < 32; o <<= 1) {
        int u = __shfl_up_sync(0xffffffffu, s, o);
        if (lane >= o) s += u;
    }
    if (lane == 31) warp_sums[wid] = s;
    __syncthreads();
    if (wid == 0) {
        int ws = warp_sums[lane];
#pragma unroll
        for (int o = 1; o < 32; o <<= 1) {
            int u = __shfl_up_sync(0xffffffffu, ws, o);
            if (lane >= o) ws += u;
        }
        warp_sums[lane] = ws;
    }
    __syncthreads();
    int excl = (s - sum) + (wid > 0 ? warp_sums[wid - 1] : 0);
#pragma unroll 4
    for (int i = 0; i < per; ++i) {
        int idx = base + i;
        if (idx < n) {
            int off = excl + local[i];
            g_off[idx] = off;
            g_cur[idx] = off;
        }
    }
    if (t == 1023) g_off[n] = excl + sum;
}
__global__ void csr_scatter(const int* __restrict__ row, const int* __restrict__ col,
                            const float* __restrict__ val, int E) {
    int e = blockIdx.x * blockDim.x + threadIdx.x;
    if (e >= E) return;
    int r = row[e];
    int slot = atomicAdd(&g_cur[r], 1);
    g_scol[slot] = col[e];
    g_sval[slot] = val[e];
}

// ---------------------------------------------------------------------------
// SpMM gather + bias + ReLU + bf16 split: writes g_xh/g_xl for next GEMM.
// ---------------------------------------------------------------------------
__global__ __launch_bounds__(128)
void spmm_gather(const float* __restrict__ bias) {
    const int r = blockIdx.x;
    const int t = threadIdx.x;
    const int beg = g_off[r];
    const int end = g_off[r + 1];
    const int c4 = t * 4;

    float4 a0 = make_float4(0.f, 0.f, 0.f, 0.f);
    float4 a1 = make_float4(0.f, 0.f, 0.f, 0.f);

    int j = beg;
    for (; j + 1 < end; j += 2) {
        int   c0 = g_scol[j],     c1 = g_scol[j + 1];
        float v0 = g_sval[j],     v1 = g_sval[j + 1];
        float4 h0 = *reinterpret_cast<const float4*>(&g_h[(size_t)c0 * HID + c4]);
        float4 h1 = *reinterpret_cast<const float4*>(&g_h[(size_t)c1 * HID + c4]);
        a0.x = fmaf(v0, h0.x, a0.x);  a0.y = fmaf(v0, h0.y, a0.y);
        a0.z = fmaf(v0, h0.z, a0.z);  a0.w = fmaf(v0, h0.w, a0.w);
        a1.x = fmaf(v1, h1.x, a1.x);  a1.y = fmaf(v1, h1.y, a1.y);
        a1.z = fmaf(v1, h1.z, a1.z);  a1.w = fmaf(v1, h1.w, a1.w);
    }
    if (j < end) {
        int   c0 = g_scol[j];
        float v0 = g_sval[j];
        float4 h0 = *reinterpret_cast<const float4*>(&g_h[(size_t)c0 * HID + c4]);
        a0.x = fmaf(v0, h0.x, a0.x);  a0.y = fmaf(v0, h0.y, a0.y);
        a0.z = fmaf(v0, h0.z, a0.z);  a0.w = fmaf(v0, h0.w, a0.w);
    }

    float4 b = *reinterpret_cast<const float4*>(&bias[c4]);
    float ox = fmaxf(a0.x + a1.x + b.x, 0.f);
    float oy = fmaxf(a0.y + a1.y + b.y, 0.f);
    float oz = fmaxf(a0.z + a1.z + b.z, 0.f);
    float ow = fmaxf(a0.w + a1.w + b.w, 0.f);

    __nv_bfloat16 h0 = __float2bfloat16(ox), h1 = __float2bfloat16(oy);
    __nv_bfloat16 h2 = __float2bfloat16(oz), h3 = __float2bfloat16(ow);
    __nv_bfloat16 l0 = __float2bfloat16(ox - __bfloat162float(h0));
    __nv_bfloat16 l1 = __float2bfloat16(oy - __bfloat162float(h1));
    __nv_bfloat16 l2 = __float2bfloat16(oz - __bfloat162float(h2));
    __nv_bfloat16 l3 = __float2bfloat16(ow - __bfloat162float(h3));
    ushort4 hv = make_ushort4(__bfloat16_as_ushort(h0), __bfloat16_as_ushort(h1),
                              __bfloat16_as_ushort(h2), __bfloat16_as_ushort(h3));
    ushort4 lv = make_ushort4(__bfloat16_as_ushort(l0), __bfloat16_as_ushort(l1),
                              __bfloat16_as_ushort(l2), __bfloat16_as_ushort(l3));
    *reinterpret_cast<ushort4*>(&g_xh[(size_t)r * HID + c4]) = hv;
    *reinterpret_cast<ushort4*>(&g_xl[(size_t)r * HID + c4]) = lv;
}

// ---------------------------------------------------------------------------
// head2: out[r] = sigmoid(dot(h[r,:], w) + b)   (one warp per row)
// ---------------------------------------------------------------------------
__global__ void head2(const float* __restrict__ w, const float* __restrict__ b,
                      float* __restrict__ out, int M) {
    int warp = (blockIdx.x * blockDim.x + threadIdx.x) >> 5;
    int lane = threadIdx.x & 31;
    if (warp >= M) return;
    const float* hr = &g_h[(size_t)warp * HID];
    float s = 0.f;
#pragma unroll
    for (int k = lane * 4; k < HID; k += 32 * 4) {
        float4 hv = *reinterpret_cast<const float4*>(&hr[k]);
        float4 wv = *reinterpret_cast<const float4*>(&w[k]);
        s = fmaf(hv.x, wv.x, s);
        s = fmaf(hv.y, wv.y, s);
        s = fmaf(hv.z, wv.z, s);
        s = fmaf(hv.w, wv.w, s);
    }
#pragma unroll
    for (int off = 16; off > 0; off >>= 1)
        s += __shfl_down_sync(0xffffffffu, s, off);
    if (lane == 0) {
        float z = s + b[0];
        out[warp] = 1.0f / (1.0f + expf(-z));
    }
}

// ---------------------------------------------------------------------------
// launch
// ---------------------------------------------------------------------------
extern "C" void kernel_launch(void* const* d_in, const int* in_sizes, int n_in,
                              void* d_out, int out_size) {
    const float* feat    = (const float*)d_in[0];
    const int*   adj_row = (const int*)d_in[1];
    const int*   adj_col = (const int*)d_in[2];
    const float* adj_val = (const float*)d_in[3];
    const float* Wg      = (const float*)d_in[4];
    const float* bg      = (const float*)d_in[5];
    const float* vw1     = (const float*)d_in[6];
    const float* vb1     = (const float*)d_in[7];
    const float* vw2     = (const float*)d_in[8];
    const float* vb2     = (const float*)d_in[9];
    float*       out     = (float*)d_out;

    const int M = in_sizes[0] / HID;   // 10000
    const int E = in_sizes[1];         // 160000
    const int n4 = (M * HID) / 4;

    float*          h_ptr;  cudaGetSymbolAddress((void**)&h_ptr,  g_h);
    __nv_bfloat16*  xh_ptr; cudaGetSymbolAddress((void**)&xh_ptr, g_xh);
    __nv_bfloat16*  xl_ptr; cudaGetSymbolAddress((void**)&xl_ptr, g_xl);
    __nv_bfloat16*  wh_ptr; cudaGetSymbolAddress((void**)&wh_ptr, g_wh);
    __nv_bfloat16*  wl_ptr; cudaGetSymbolAddress((void**)&wl_ptr, g_wl);

    // --- CSR build + weight/feat conversion ---
    csr_zero<<<(M + 255) / 256, 256>>>(M);
    csr_hist<<<(E + 255) / 256, 256>>>(adj_row, E);
    csr_scan<<<1, 1024>>>(M);
    csr_scatter<<<(E + 255) / 256, 256>>>(adj_row, adj_col, adj_val, E);
    wconv<<<dim3(HID / 32, HID / 32, 6), dim3(32, 8)>>>(Wg, vw1);
    conv_act<<<(n4 + 255) / 256, 256>>>(feat, n4);

    const int mb = (M + BM - 1) / BM;
    dim3 gGrid(HID / BN, mb);   // (4, 79)

    for (int layer = 0; layer < 5; ++layer) {
        gemm_hmma<0><<<gGrid, 256>>>(xh_ptr, xl_ptr,
                                     wh_ptr + (size_t)layer * HID * HID,
                                     wl_ptr + (size_t)layer * HID * HID,
                                     h_ptr, nullptr, M);
        spmm_gather<<<M, 128>>>(bg + (size_t)layer * HID);
    }

    // h = relu(x @ vw1 + vb1)
    gemm_hmma<1><<<gGrid, 256>>>(xh_ptr, xl_ptr,
                                 wh_ptr + (size_t)5 * HID * HID,
                                 wl_ptr + (size_t)5 * HID * HID,
                                 h_ptr, vb1, M);
    // out = sigmoid(h @ vw2 + vb2)
    head2<<<(M * 32 + 255) / 256, 256>>>(vw2, vb2, out, M);
}